// round 10
// baseline (speedup 1.0000x reference)
#include <cuda_runtime.h>

// LocalVariation: out[b, k, y, x] = x[b,0,y,x] - x_pad[b,0,y+i,x+j]
// 24 off-center (i,j) in 5x5 window, replicate padding.
// x [16,1,512,512] f32 -> out [16,24,512,512] f32.
//
// R10 = R9 (vectorized halo: LDG.128 + 2x STS.64 interior, scalar clamped
// edges; rolling 2-row window; float4 __stcs) + R5 wave-tail fix:
// non-uniform row tiles per 512-row strip: 2x16 + 32x15 = 34 tiles.
// Grid 4 x 34 x 16 = 2176 blocks; 760 resident (5/SM x 152 SM) ->
// idle tail ~4.6% vs ~10% at 2048 uniform.

#define HH 512
#define WW 512
#define NB 16
#define NC 24
#define TX 128    // tile width (32 threads x float4)
#define SW 132    // TX + 4 halo
#define SHMAX 20  // max tile height (16) + 4 halo

__global__ __launch_bounds__(256, 5)
void local_variation_kernel(const float* __restrict__ x, float* __restrict__ out) {
    __shared__ float s[SHMAX][SW];

    const int warp = threadIdx.y;     // 0..7
    const int lane = threadIdx.x;     // 0..31
    const int x0 = blockIdx.x * TX;
    const int by = blockIdx.y;
    const int b  = blockIdx.z;

    // Non-uniform tile heights: by 0,1 -> 16 rows; by 2..33 -> 15 rows.
    const int h  = (by < 2) ? 16 : 15;
    const int y0 = (by < 2) ? (16 * by) : (32 + 15 * (by - 2));
    const int sh = h + 4;

    const float* __restrict__ xb = x + (size_t)b * HH * WW;

    // ---- Vectorized halo fill: one warp per smem row ----
    // Interior halo cols c = 2+4*lane .. 5+4*lane <-> gx = x0+4*lane .. +3
    // (always in-image, gmem 16B-aligned). Smem col 2+4*lane is 8B-aligned:
    // store the float4 as two float2 (STS.64). Lanes 0..3 cover the
    // x-clamped edge cols 0,1,130,131 as scalars.
    for (int r = warp; r < sh; r += 8) {
        const int gy = min(max(y0 + r - 2, 0), HH - 1);
        const float* __restrict__ row = xb + gy * WW;

        float4 v = *reinterpret_cast<const float4*>(row + x0 + 4 * lane);
        *reinterpret_cast<float2*>(&s[r][2 + 4 * lane]) = make_float2(v.x, v.y);
        *reinterpret_cast<float2*>(&s[r][4 + 4 * lane]) = make_float2(v.z, v.w);

        if (lane < 4) {
            int c  = (lane < 2) ? lane : (128 + lane);   // 0,1,130,131
            int gx = min(max(x0 + c - 2, 0), WW - 1);
            s[r][c] = row[gx];
        }
    }
    __syncthreads();

    const int sx = lane * 4;          // tile-local col of first pixel
    const int rb = warp * 2;          // first output row (tile-local)
    const bool row1 = (rb + 1) < h;   // warp-uniform; false only for warp 7 @ h=15

    // 5-row x 8-float rolling register window.
    float w[5][8];
    #pragma unroll
    for (int i = 0; i < 5; i++) {
        float4 lo = *reinterpret_cast<const float4*>(&s[rb + i][sx]);
        float4 hi = *reinterpret_cast<const float4*>(&s[rb + i][sx + 4]);
        w[i][0] = lo.x; w[i][1] = lo.y; w[i][2] = lo.z; w[i][3] = lo.w;
        w[i][4] = hi.x; w[i][5] = hi.y; w[i][6] = hi.z; w[i][7] = hi.w;
    }

    const int gy0 = y0 + rb;
    const int gx  = x0 + sx;
    float* __restrict__ ob = out + (((size_t)b * NC) * HH + gy0) * WW + gx;
    const size_t plane = (size_t)HH * WW;

    // ---- row 0 (always valid) ----
    {
        const float c0 = w[2][2], c1 = w[2][3], c2 = w[2][4], c3 = w[2][5];
        int k = 0;
        #pragma unroll
        for (int i = 0; i < 5; i++) {
            const float* rr = w[i];
            #pragma unroll
            for (int j = 0; j < 5; j++) {
                if (i == 2 && j == 2) continue;
                float4 o;
                o.x = c0 - rr[j + 0];
                o.y = c1 - rr[j + 1];
                o.z = c2 - rr[j + 2];
                o.w = c3 - rr[j + 3];
                __stcs(reinterpret_cast<float4*>(ob + (size_t)k * plane), o);
                k++;
            }
        }
    }

    // ---- roll + row 1 (warp-uniform predicate) ----
    if (row1) {
        {
            float4 lo = *reinterpret_cast<const float4*>(&s[rb + 5][sx]);
            float4 hi = *reinterpret_cast<const float4*>(&s[rb + 5][sx + 4]);
            float* d = w[0];
            d[0] = lo.x; d[1] = lo.y; d[2] = lo.z; d[3] = lo.w;
            d[4] = hi.x; d[5] = hi.y; d[6] = hi.z; d[7] = hi.w;
        }
        const float c0 = w[3][2], c1 = w[3][3], c2 = w[3][4], c3 = w[3][5];
        float* __restrict__ orow = ob + WW;
        int k = 0;
        #pragma unroll
        for (int i = 0; i < 5; i++) {
            const float* rr = w[(1 + i) % 5];
            #pragma unroll
            for (int j = 0; j < 5; j++) {
                if (i == 2 && j == 2) continue;
                float4 o;
                o.x = c0 - rr[j + 0];
                o.y = c1 - rr[j + 1];
                o.z = c2 - rr[j + 2];
                o.w = c3 - rr[j + 3];
                __stcs(reinterpret_cast<float4*>(orow + (size_t)k * plane), o);
                k++;
            }
        }
    }
}

extern "C" void kernel_launch(void* const* d_in, const int* in_sizes, int n_in,
                              void* d_out, int out_size) {
    const float* x = (const float*)d_in[0];
    float* out = (float*)d_out;
    dim3 block(32, 8, 1);
    dim3 grid(WW / TX, 34, NB);   // 4 x 34 x 16 = 2176 blocks
    local_variation_kernel<<<grid, block>>>(x, out);
}